// round 15
// baseline (speedup 1.0000x reference)
#include <cuda_runtime.h>
#include <cstdint>

// Problem constants
#define NB    1024
#define NTCR  100
#define NFEAT 15
#define NAA   24
#define NCH   14          // total conv output channels
#define NINST (NB*NTCR)   // 102400
#define INSTB 64          // instances per block (32 f32x2 pairs)
#define NBLK_CONV (NINST/INSTB) // 1600
#define CONV_THREADS 448  // 14 warps: warp = ONE channel, lane = instance pair
#define XT_WORDS (360*66) // transposed x tile [r][inst], 64 inst + 2 pad -> conflict-free
#define XT_BYTES (XT_WORDS*4) // 95040 B dynamic smem

// ---------------- scratch (static device memory; no allocation) ----------------
__device__ float g_hbuf[NINST * NCH];           // h vectors (per instance)
__device__ float g_sbuf[NINST];                 // attention scores
__device__ float g_zbuf[NB * NCH];              // decoder_f output (pre-BN)
__device__ unsigned long long g_wpack2[1470];   // conv weights, duplicated f32x2 halves
__device__ float g_wbias[14];                   // conv biases

// Diagnostic: keeps convKernel at ncu's captured launch index (-s 5 -c 1).
__global__ void dummyKernel() {}

// ---------------- f32x2 helpers ----------------
__device__ __forceinline__ unsigned long long ffma2(unsigned long long a,
                                                    unsigned long long b,
                                                    unsigned long long c) {
    unsigned long long d;
    asm("fma.rn.f32x2 %0, %1, %2, %3;" : "=l"(d) : "l"(a), "l"(b), "l"(c));
    return d;
}
__device__ __forceinline__ float lo2(unsigned long long v) {
    return __uint_as_float((unsigned)(v & 0xffffffffull));
}
__device__ __forceinline__ float hi2(unsigned long long v) {
    return __uint_as_float((unsigned)(v >> 32));
}
__device__ __forceinline__ unsigned long long pack2h(float a, float b) {
    unsigned long long lo = __float_as_uint(a);
    unsigned long long hi = __float_as_uint(b);
    return (hi << 32) | lo;
}

// ---------------- prep: pack conv weights, layout [c][ch*7 + t], dup halves ----------------
__global__ void prepKernel(const float* __restrict__ w0, const float* __restrict__ b0,
                           const float* __restrict__ w1, const float* __restrict__ b1,
                           const float* __restrict__ w2, const float* __restrict__ b2,
                           const float* __restrict__ w3, const float* __restrict__ b3,
                           const float* __restrict__ w4, const float* __restrict__ b4,
                           const float* __restrict__ w5, const float* __restrict__ b5) {
    const int chH[14]    = {2,2,2,3,3,3,4,4,4,5,5,6,6,7};
    const int chF[14]    = {0,1,2,0,1,2,0,1,2,0,1,0,1,0};
    const int chConv[14] = {0,0,0,1,1,1,2,2,2,3,3,4,4,5};
    const float* cws[6] = {w0,w1,w2,w3,w4,w5};
    const float* cbs[6] = {b0,b1,b2,b3,b4,b5};
    int idx = blockIdx.x * blockDim.x + threadIdx.x;
    if (idx < 1470) {
        int c  = idx / 98;
        int r  = idx - c * 98;
        int ch = r / 7;
        int t  = r - ch * 7;
        int h  = chH[ch];
        float w = 0.0f;
        if (t < h) {
            const float* W = cws[chConv[ch]];
            w = W[(chF[ch] * NFEAT + c) * h + t];
        }
        g_wpack2[idx] = pack2h(w, w);
    } else if (idx < 1484) {
        int ch = idx - 1470;
        g_wbias[ch] = cbs[chConv[ch]][chF[ch]];
    }
}

// ---------------- conv body: one channel per warp, streaming x, exact taps ----------------
template<int H>
__device__ __forceinline__ void convBody1(const float* __restrict__ xt_lane,
                                          const unsigned long long* __restrict__ wch,
                                          float& mlo, float& mhi) {
    unsigned long long acc[25 - H];
    #pragma unroll
    for (int p = 0; p <= 24 - H; ++p) acc[p] = 0ull;

    #pragma unroll 1
    for (int c = 0; c < 15; ++c) {
        unsigned long long wt[H];
        #pragma unroll
        for (int t = 0; t < H; ++t) wt[t] = wch[c * 98 + t];

        const float* xr = xt_lane + c * (24 * 66);
        #pragma unroll
        for (int u = 0; u < 24; ++u) {
            unsigned long long xv = *(const unsigned long long*)(xr + u * 66);
            #pragma unroll
            for (int t = 0; t < H; ++t) {
                if (t <= u && (u - t) <= 24 - H)
                    acc[u - t] = ffma2(wt[t], xv, acc[u - t]);
            }
        }
    }

    float alo = lo2(acc[0]), ahi = hi2(acc[0]);
    #pragma unroll
    for (int p = 1; p <= 24 - H; ++p) {
        alo = fmaxf(alo, lo2(acc[p]));
        ahi = fmaxf(ahi, hi2(acc[p]));
    }
    mlo = alo; mhi = ahi;
}

// ---------------- stage 1: conv + relu + maxpool + fc1 + relu + score ----------------
extern __shared__ float xt[];   // [360][66]: word r*66 + inst; pairs read LDS.64 at 2*pair

__global__ void __launch_bounds__(CONV_THREADS, 2) convKernel(const float* __restrict__ x,
                                                              const float* __restrict__ fc1w,
                                                              const float* __restrict__ fc1b,
                                                              const float* __restrict__ waw) {
    __shared__ float fcw[196];
    __shared__ float fcb[16];
    __shared__ float wav[16];
    __shared__ float wbias[16];

    int tid  = threadIdx.x;
    int w    = tid >> 5;      // 0..13 = channel
    int lane = tid & 31;      // instance pair within block
    int instBase = blockIdx.x * INSTB;

    if (tid < 196) fcw[tid] = fc1w[tid];   // 448 threads cover 196
    if (tid < 16) {
        fcb[tid]   = (tid < 14) ? fc1b[tid] : 0.0f;
        wav[tid]   = (tid < 14) ? waw[tid]  : 0.0f;
        wbias[tid] = (tid < 14) ? g_wbias[tid] : 0.0f;
    }

    // Fill transposed tile: e linear in x (coalesced LDG); incremental wrap.
    {
        const float* xg = x + (size_t)instBase * 360;
        int r = tid % 360, inst = tid / 360;
        for (int e = tid; e < INSTB * 360; e += CONV_THREADS) {
            xt[r * 66 + inst] = xg[e];
            r += CONV_THREADS;
            while (r >= 360) { r -= 360; ++inst; }
        }
    }
    __syncthreads();

    const float* xt_lane = xt + 2 * lane;
    const unsigned long long* wch = g_wpack2 + w * 7;

    // heights per channel: {2,2,2,3,3,3,4,4,4,5,5,6,6,7}
    float mlo, mhi;
    switch (w) {
        case 0: case 1: case 2:   convBody1<2>(xt_lane, wch, mlo, mhi); break;
        case 3: case 4: case 5:   convBody1<3>(xt_lane, wch, mlo, mhi); break;
        case 6: case 7: case 8:   convBody1<4>(xt_lane, wch, mlo, mhi); break;
        case 9: case 10:          convBody1<5>(xt_lane, wch, mlo, mhi); break;
        case 11: case 12:         convBody1<6>(xt_lane, wch, mlo, mhi); break;
        default:                  convBody1<7>(xt_lane, wch, mlo, mhi); break;
    }

    // alias feats/scs into xt: barrier ensures ALL warps finished reading xt
    float* feats = xt;                      // [64][17]
    float* scs   = xt + INSTB * 17;         // [64][14]
    __syncthreads();

    {
        float b = wbias[w];
        feats[(2 * lane)     * 17 + w] = fmaxf(mlo + b, 0.0f);
        feats[(2 * lane + 1) * 17 + w] = fmaxf(mhi + b, 0.0f);
    }
    __syncthreads();

    // fc1 + relu + score terms: 64*14 = 896 items over 448 threads (2 each)
    for (int item = tid; item < INSTB * 14; item += CONV_THREADS) {
        int ii = item / 14;
        int j  = item - ii * 14;
        float hv = fcb[j];
        #pragma unroll
        for (int k = 0; k < 14; ++k)
            hv = fmaf(fcw[j * 14 + k], feats[ii * 17 + k], hv);
        hv = fmaxf(hv, 0.0f);
        g_hbuf[(size_t)(instBase + ii) * 14 + j] = hv;
        scs[ii * 14 + j] = hv * wav[j];
    }
    __syncthreads();

    if (tid < INSTB) {
        float s = 0.0f;
        #pragma unroll
        for (int j = 0; j < 14; ++j) s += scs[tid * 14 + j];
        g_sbuf[instBase + tid] = s;
    }
}

// ---------------- stage 2: sparsemax + pooled + decoder_f (one block per repertoire) ----------------
__global__ void __launch_bounds__(128) attnKernel(const float* __restrict__ decfw,
                                                  const float* __restrict__ decfb,
                                                  float* __restrict__ out,
                                                  int write_attw) {
    __shared__ float z[100];
    __shared__ float zsrt[100];
    __shared__ float csh[100];
    __shared__ float aw[100];
    __shared__ float hsh[1400];
    __shared__ float pooled[14];
    __shared__ int   ks_sh;

    int b = blockIdx.x;
    int t = threadIdx.x;

    if (t == 0) ks_sh = 1;
    if (t < 100) z[t] = g_sbuf[b * 100 + t];
    for (int i = t; i < 1400; i += 128) hsh[i] = g_hbuf[b * 1400 + i];
    __syncthreads();

    // exact O(n^2) rank sort (descending, stable)
    if (t < 100) {
        float zi = z[t];
        int r = 0;
        for (int j2 = 0; j2 < 100; ++j2) {
            float zj = z[j2];
            r += (int)(zj > zi) | ((int)(zj == zi) & (int)(j2 < t));
        }
        zsrt[r] = zi;
    }
    __syncthreads();

    // parallel cumsum (triangular) + support-size via atomicMax
    if (t < 100) {
        float cs = 0.0f;
        for (int i2 = 0; i2 <= t; ++i2) cs += zsrt[i2];
        csh[t] = cs;
        if (1.0f + (float)(t + 1) * zsrt[t] > cs) atomicMax(&ks_sh, t + 1);
    }
    __syncthreads();

    int   ks  = ks_sh;
    float tau = (csh[ks - 1] - 1.0f) / (float)ks;

    if (t < 100) {
        float a = fmaxf(z[t] - tau, 0.0f);
        aw[t] = a;
        if (write_attw) out[2048 + b * 100 + t] = a;
    }
    __syncthreads();

    if (t < 14) {
        float acc = 0.0f;
        #pragma unroll 4
        for (int p = 0; p < 100; ++p)
            acc = fmaf(aw[p], hsh[p * 14 + t], acc);
        pooled[t] = acc;
    }
    __syncthreads();

    if (t < 14) {
        float zz = decfb[t];
        #pragma unroll
        for (int k = 0; k < 14; ++k) zz = fmaf(decfw[t * 14 + k], pooled[k], zz);
        g_zbuf[b * 14 + t] = zz;
    }
}

// ---------------- stage 3: batchnorm (batch stats) + relu + decoder_s ----------------
__global__ void __launch_bounds__(1024) bnKernel(const float* __restrict__ bng,
                                                 const float* __restrict__ bnb,
                                                 const float* __restrict__ dsw,
                                                 const float* __restrict__ dsb,
                                                 float* __restrict__ out) {
    __shared__ float ssum[32][14];
    __shared__ float ssq[32][14];
    __shared__ float mu[14];
    __shared__ float sc[14];

    int b    = threadIdx.x;
    int w    = b >> 5;
    int lane = b & 31;

    float zr[14];
    #pragma unroll
    for (int j = 0; j < 14; ++j) zr[j] = g_zbuf[b * 14 + j];

    #pragma unroll
    for (int j = 0; j < 14; ++j) {
        float s = zr[j];
        float q = zr[j] * zr[j];
        #pragma unroll
        for (int off = 16; off; off >>= 1) {
            s += __shfl_xor_sync(0xffffffffu, s, off);
            q += __shfl_xor_sync(0xffffffffu, q, off);
        }
        if (lane == 0) { ssum[w][j] = s; ssq[w][j] = q; }
    }
    __syncthreads();

    if (b < 14) {
        float s = 0.0f, q = 0.0f;
        #pragma unroll
        for (int i = 0; i < 32; ++i) { s += ssum[i][b]; q += ssq[i][b]; }
        float m = s * (1.0f / 1024.0f);
        float v = q * (1.0f / 1024.0f) - m * m;
        mu[b] = m;
        sc[b] = bng[b] * rsqrtf(v + 1e-5f);
    }
    __syncthreads();

    float l0 = dsb[0], l1 = dsb[1];
    #pragma unroll
    for (int j = 0; j < 14; ++j) {
        float zn = fmaxf((zr[j] - mu[j]) * sc[j] + bnb[j], 0.0f);
        l0 = fmaf(dsw[j],      zn, l0);
        l1 = fmaf(dsw[14 + j], zn, l1);
    }
    out[b * 2]     = l0;
    out[b * 2 + 1] = l1;
}

// ---------------- launch ----------------
extern "C" void kernel_launch(void* const* d_in, const int* in_sizes, int n_in,
                              void* d_out, int out_size) {
    static const int MAP_INS[22] = {0,1,2,3,4,5,6,7,8,9,10,11,12,13,14,15,16,17,18,19,20,21};
    //                       x  cw0 cb0 cw1 cb1 cw2 cb2 cw3 cb3 cw4 cb4 cw5 cb5 f1w f1b waw dfw dfb bng bnb dsw dsb
    static const int MAP_AL[22] = {21, 8,  2,  9,  3, 10,  4, 11,  5, 12,  6, 13,  7, 19, 18, 20, 15, 14,  1,  0, 17, 16};

    const int* M = MAP_INS;
    if (n_in >= 22 && in_sizes[0] != NINST * NFEAT * NAA && in_sizes[21] == NINST * NFEAT * NAA) {
        M = MAP_AL;
    }

    const float* x    = (const float*)d_in[M[0]];
    const float* cw0  = (const float*)d_in[M[1]];
    const float* cb0  = (const float*)d_in[M[2]];
    const float* cw1  = (const float*)d_in[M[3]];
    const float* cb1  = (const float*)d_in[M[4]];
    const float* cw2  = (const float*)d_in[M[5]];
    const float* cb2  = (const float*)d_in[M[6]];
    const float* cw3  = (const float*)d_in[M[7]];
    const float* cb3  = (const float*)d_in[M[8]];
    const float* cw4  = (const float*)d_in[M[9]];
    const float* cb4  = (const float*)d_in[M[10]];
    const float* cw5  = (const float*)d_in[M[11]];
    const float* cb5  = (const float*)d_in[M[12]];
    const float* fc1w = (const float*)d_in[M[13]];
    const float* fc1b = (const float*)d_in[M[14]];
    const float* waw  = (const float*)d_in[M[15]];
    const float* dfw  = (const float*)d_in[M[16]];
    const float* dfb  = (const float*)d_in[M[17]];
    const float* bng  = (const float*)d_in[M[18]];
    const float* bnb  = (const float*)d_in[M[19]];
    const float* dsw  = (const float*)d_in[M[20]];
    const float* dsb  = (const float*)d_in[M[21]];
    float* out = (float*)d_out;

    int write_attw = (out_size >= 2048 + NB * NTCR) ? 1 : 0;

    // opt-in to >48KB dynamic shared memory (idempotent, not an allocation)
    static int attr_done = 0;
    if (!attr_done) {
        cudaFuncSetAttribute(convKernel, cudaFuncAttributeMaxDynamicSharedMemorySize, XT_BYTES);
        attr_done = 1;
    }

    dummyKernel<<<1, 32>>>();
    dummyKernel<<<1, 32>>>();
    prepKernel<<<6, 256>>>(cw0, cb0, cw1, cb1, cw2, cb2, cw3, cb3, cw4, cb4, cw5, cb5);
    convKernel<<<NBLK_CONV, CONV_THREADS, XT_BYTES>>>(x, fc1w, fc1b, waw);
    attnKernel<<<NB, 128>>>(dfw, dfb, out, write_attw);
    bnKernel<<<1, 1024>>>(bng, bnb, dsw, dsb, out);
}